// round 2
// baseline (speedup 1.0000x reference)
#include <cuda_runtime.h>

// ---------------- NAVAR dims ----------------
#define ND      2
#define NS      4
#define NV      12
#define HID     16
#define GROUPS  96
#define KS      4
#define T       2048
#define BATCH   8

// ---------------- tiling ----------------
#define TT      228              // output timesteps per tile
#define HALO    28               // 3 + 3*(1+2+4)
#define LL      (TT + HALO)      // 256 local positions
#define PITCH   264              // row pitch (floats), >= LL + 8 for overshoot
#define NTHREADS 256
#define NWARP    8
#define NTILES  ((T + TT - 1) / TT)          // 9
#define PRED_ELEMS (BATCH*ND*NS*NV*T)        // 1,572,864

struct __align__(16) Smem {
    float bufA[HID * PITCH];     // 16896 B
    float bufB[HID * PITCH];     // 16896 B
    float xs[PITCH];             // 1056 B
    float whs[HID * HID * KS];   // 4096 B (one hidden layer's weights)
    float w_in[HID * KS];        // 256 B
    float b_in[HID];
    float b_h[3 * HID];
    float w_out[NV * HID];       // 768 B
    float b_out[NV];
};  // ~40.5 KB static shared

// Input conv: 1 -> HID, dilation 1.  Computes h0 for local j in [4, LL).
__device__ __forceinline__ void input_layer(
    const float* __restrict__ xs, float* __restrict__ out,
    const float* __restrict__ wi, const float* __restrict__ bi,
    int gt0, int lane, int wid)
{
    const int S = 4;      // first computed j
    const int A = 4;      // aligned left extent of load window
    for (int co = wid; co < HID; co += NWARP) {
        int j0 = S + lane * 8;
        if (j0 >= LL) continue;
        const float4 w = *(const float4*)(wi + co * 4);
        const float  b = bi[co];
        const float* row = xs + (j0 - A);
        float v[12];
        #pragma unroll
        for (int q = 0; q < 3; q++) {
            float4 t4 = *(const float4*)(row + 4 * q);
            v[4*q+0] = t4.x; v[4*q+1] = t4.y; v[4*q+2] = t4.z; v[4*q+3] = t4.w;
        }
        const int base = A - 3;   // = 1
        float acc[8];
        #pragma unroll
        for (int m = 0; m < 8; m++) {
            float a = b;
            a = fmaf(w.x, v[base + m + 0], a);
            a = fmaf(w.y, v[base + m + 1], a);
            a = fmaf(w.z, v[base + m + 2], a);
            a = fmaf(w.w, v[base + m + 3], a);
            acc[m] = a;
        }
        float* orow = out + co * PITCH;
        #pragma unroll
        for (int m = 0; m < 8; m++) {
            int j = j0 + m;
            if (j < LL) {
                float val = fmaxf(acc[m], 0.f);
                if (gt0 + j < 0) val = 0.f;     // causal zero-padding region
                orow[j] = val;
            }
        }
    }
}

// Hidden conv: HID -> HID, dilation D.  Computes out for local j in [S, LL).
// A = aligned left extent (4*ceil(3D/4)).  Valid input range is [S - 3D, LL).
template<int D, int A, int S>
__device__ __forceinline__ void hidden_layer(
    const float* __restrict__ in, float* __restrict__ out,
    const float* __restrict__ wl, const float* __restrict__ bl,
    int gt0, int lane, int wid)
{
    for (int co = wid; co < HID; co += NWARP) {
        int j0 = S + lane * 8;
        if (j0 >= LL) continue;
        const float b = bl[co];
        float acc[8];
        #pragma unroll
        for (int m = 0; m < 8; m++) acc[m] = b;

        #pragma unroll
        for (int ci = 0; ci < HID; ci++) {
            const float4 w = *(const float4*)(wl + (co * HID + ci) * 4);
            const float* row = in + ci * PITCH + (j0 - A);
            float v[A + 8];
            #pragma unroll
            for (int q = 0; q < (A + 8) / 4; q++) {
                float4 t4 = *(const float4*)(row + 4 * q);
                v[4*q+0] = t4.x; v[4*q+1] = t4.y; v[4*q+2] = t4.z; v[4*q+3] = t4.w;
            }
            const int base = A - 3 * D;
            #pragma unroll
            for (int m = 0; m < 8; m++) {
                acc[m] = fmaf(w.x, v[base + m + 0*D], acc[m]);
                acc[m] = fmaf(w.y, v[base + m + 1*D], acc[m]);
                acc[m] = fmaf(w.z, v[base + m + 2*D], acc[m]);
                acc[m] = fmaf(w.w, v[base + m + 3*D], acc[m]);
            }
        }
        float* orow = out + co * PITCH;
        #pragma unroll
        for (int m = 0; m < 8; m++) {
            int j = j0 + m;
            if (j < LL) {
                float val = fmaxf(acc[m], 0.f);
                if (gt0 + j < 0) val = 0.f;     // causal zero-padding region
                orow[j] = val;
            }
        }
    }
}

__global__ void __launch_bounds__(NTHREADS, 2)
navar_main_kernel(const float* __restrict__ x,
                  const float* __restrict__ w_in, const float* __restrict__ b_in,
                  const float* __restrict__ w_h,  const float* __restrict__ b_h,
                  const float* __restrict__ w_out,const float* __restrict__ b_out,
                  float* __restrict__ out_contrib)
{
    __shared__ Smem s;
    const int tile = blockIdx.x;
    const int g    = blockIdx.y;
    const int b    = blockIdx.z;
    const int t0   = tile * TT;
    const int gt0  = t0 - HALO;            // local j=0 <-> global time gt0
    const int tid  = threadIdx.x;
    const int lane = tid & 31;
    const int wid  = tid >> 5;

    // ---- stage x tile + small weights ----
    const float* xg = x + ((size_t)b * GROUPS + g) * T;
    for (int j = tid; j < PITCH; j += NTHREADS) {
        int gt = gt0 + j;
        s.xs[j] = (gt >= 0 && gt < T) ? xg[gt] : 0.f;
    }
    for (int i = tid; i < HID * KS; i += NTHREADS) s.w_in[i] = w_in[g * HID * KS + i];
    for (int i = tid; i < HID;      i += NTHREADS) s.b_in[i] = b_in[g * HID + i];
    for (int i = tid; i < 3 * HID;  i += NTHREADS) {
        int layer = i / HID, co = i % HID;
        s.b_h[i] = b_h[layer * GROUPS * HID + g * HID + co];
    }
    for (int i = tid; i < NV * HID; i += NTHREADS) s.w_out[i] = w_out[g * NV * HID + i];
    for (int i = tid; i < NV;       i += NTHREADS) s.b_out[i] = b_out[g * NV + i];
    __syncthreads();

    // ---- layer 0: input conv -> bufA ----
    input_layer(s.xs, s.bufA, s.w_in, s.b_in, gt0, lane, wid);

    // ---- 3 dilated hidden layers (ping-pong A->B->A->B) ----
    #pragma unroll 1
    for (int L = 0; L < 3; L++) {
        __syncthreads();                       // prev compute done (buffers + whs free)
        const float* wsrc = w_h + ((size_t)L * GROUPS * HID + g * HID) * (HID * KS);
        for (int i = tid; i < HID * HID * KS; i += NTHREADS) s.whs[i] = wsrc[i];
        __syncthreads();
        if      (L == 0) hidden_layer<1, 4,  8>(s.bufA, s.bufB, s.whs, s.b_h + 0*HID, gt0, lane, wid);
        else if (L == 1) hidden_layer<2, 8, 16>(s.bufB, s.bufA, s.whs, s.b_h + 1*HID, gt0, lane, wid);
        else             hidden_layer<4,12, 28>(s.bufA, s.bufB, s.whs, s.b_h + 2*HID, gt0, lane, wid);
    }
    __syncthreads();

    // ---- 1x1 output conv from bufB; write contributions (b,dd,ss,dst,src,t) ----
    const int dd  = g / (NS * NV);
    const int rem = g % (NS * NV);
    const int ss  = rem / NV;
    const int src = rem % NV;
    const size_t cbase = ((size_t)(((b * ND + dd) * NS + ss)) * NV * NV + src) * T;

    for (int idx = tid; idx < NV * TT; idx += NTHREADS) {
        int dst  = idx / TT;
        int trel = idx - dst * TT;
        int gt   = t0 + trel;
        if (gt >= T) continue;
        int j = HALO + trel;
        float acc = s.b_out[dst];
        #pragma unroll
        for (int ci = 0; ci < HID; ci++)
            acc = fmaf(s.w_out[dst * HID + ci], s.bufB[ci * PITCH + j], acc);
        out_contrib[cbase + (size_t)dst * NV * T + gt] = acc;
    }
}

// prediction[b,dd,ss,v,t] = sum_src contrib[b,dd,ss,v,src,t] + biases[dd,ss,v]
__global__ void __launch_bounds__(256)
navar_pred_kernel(const float* __restrict__ contrib,
                  const float* __restrict__ biases,
                  float* __restrict__ pred)
{
    int idx = blockIdx.x * blockDim.x + threadIdx.x;
    if (idx >= PRED_ELEMS) return;
    int t = idx & (T - 1);
    int r = idx >> 11;                    // T = 2048 = 2^11
    float acc = biases[r % (ND * NS * NV)];
    const float* cp = contrib + (size_t)r * NV * T + t;
    #pragma unroll
    for (int sidx = 0; sidx < NV; sidx++) acc += cp[(size_t)sidx * T];
    pred[idx] = acc;
}

extern "C" void kernel_launch(void* const* d_in, const int* in_sizes, int n_in,
                              void* d_out, int out_size)
{
    const float* x      = (const float*)d_in[0];
    const float* w_in   = (const float*)d_in[1];
    const float* b_in   = (const float*)d_in[2];
    const float* w_h    = (const float*)d_in[3];
    const float* b_h    = (const float*)d_in[4];
    const float* w_out  = (const float*)d_in[5];
    const float* b_out  = (const float*)d_in[6];
    const float* biases = (const float*)d_in[7];

    float* out     = (float*)d_out;
    float* pred    = out;                     // (B,ND,NS,NV,T)
    float* contrib = out + PRED_ELEMS;        // (B,ND,NS,NV,NV,T)

    dim3 grid(NTILES, GROUPS, BATCH);
    navar_main_kernel<<<grid, NTHREADS>>>(x, w_in, b_in, w_h, b_h, w_out, b_out, contrib);
    navar_pred_kernel<<<(PRED_ELEMS + 255) / 256, 256>>>(contrib, biases, pred);
}

// round 3
// speedup vs baseline: 2.0086x; 2.0086x over previous
#include <cuda_runtime.h>

// ---------------- NAVAR dims ----------------
#define ND      2
#define NS      4
#define NV      12
#define HID     16
#define GROUPS  96
#define KS      4
#define T       2048
#define BATCH   8

// ---------------- tiling ----------------
#define TT      228              // output timesteps per tile
#define HALO    28               // 3 + 3*(1+2+4)
#define LL      (TT + HALO)      // 256 local positions
#define PITCH   264              // row pitch (floats)
#define NTHREADS 256
#define NTILES  9
#define PRED_ELEMS (BATCH*ND*NS*NV*T)        // 1,572,864
#define GUARD   16               // floats of scratch before bufA (negative-j reads)

typedef unsigned long long u64;

// ---- packed f32x2 helpers (Blackwell) ----
__device__ __forceinline__ u64 pk2(float a, float b) {
    u64 r; asm("mov.b64 %0, {%1, %2};" : "=l"(r) : "f"(a), "f"(b)); return r;
}
__device__ __forceinline__ u64 dup2f(float a) {
    u64 r; asm("mov.b64 %0, {%1, %1};" : "=l"(r) : "f"(a)); return r;
}
__device__ __forceinline__ void fma2(u64 &d, u64 a, u64 b) {
    asm("fma.rn.f32x2 %0, %1, %2, %0;" : "+l"(d) : "l"(a), "l"(b));
}
__device__ __forceinline__ void unpk(u64 v, float &lo, float &hi) {
    asm("mov.b64 {%0, %1}, %2;" : "=f"(lo), "=f"(hi) : "l"(v));
}

struct __align__(16) Smem {
    float bufs[GUARD + 2 * HID * PITCH]; // bufA, bufB back-to-back (bufB guard = bufA tail)
    float xsb[4 + PITCH];                // 4-float guard for xs[j-3]
    u64   whp[HID * 8 * 4];              // hidden weights packed: (ci, co-pair, tap) -> (co_even, co_odd)
    u64   woutp[HID * 6];                // output weights packed: (ci, dst-pair)
    u64   boutp[6];                      // output bias pairs
    float w_in[HID * KS];
    float b_in[HID];
    float b_h[3 * HID];
};  // ~40.4 KB

// Hidden conv HID->HID, dilation D, valid outputs j in [S, LL).
// Warp layout: cg = wid>>2 selects co 8*cg..8*cg+7 (4 packed pairs);
// tq = wid&3 selects 64-timestep quarter; lane handles j1 = tq*64+lane and j2 = j1+32.
template<int D, int S>
__device__ __forceinline__ void hidden2(
    const float* __restrict__ in, float* __restrict__ out,
    const u64* __restrict__ wp, const float* __restrict__ bl,
    int gt0, int lane, int wid)
{
    const int cg = wid >> 2;
    const int tq = wid & 3;
    const int j1 = tq * 64 + lane;       // 0..223
    const int j2 = j1 + 32;              // 32..255 (always >= S since S<=28<32)

    u64 acc[4][2];
    #pragma unroll
    for (int p = 0; p < 4; p++) {
        u64 bp = pk2(bl[cg * 8 + 2 * p], bl[cg * 8 + 2 * p + 1]);
        acc[p][0] = bp; acc[p][1] = bp;
    }

    #pragma unroll 2
    for (int ci = 0; ci < HID; ci++) {
        // 16 packed weights (4 pairs x 4 taps) via 8 broadcast LDS.128
        u64 wd[16];
        const ulonglong2* w2 = (const ulonglong2*)(wp + ci * 32 + cg * 16);
        #pragma unroll
        for (int q = 0; q < 8; q++) { ulonglong2 t = w2[q]; wd[2*q] = t.x; wd[2*q+1] = t.y; }

        const float* row = in + ci * PITCH;
        u64 vda[4], vdb[4];
        #pragma unroll
        for (int k = 0; k < 4; k++) {
            vda[k] = dup2f(row[j1 + (k - 3) * D]);   // tap k multiplies x[t-(3-k)D]
            vdb[k] = dup2f(row[j2 + (k - 3) * D]);
        }
        #pragma unroll
        for (int p = 0; p < 4; p++)
            #pragma unroll
            for (int k = 0; k < 4; k++) {
                fma2(acc[p][0], wd[p * 4 + k], vda[k]);
                fma2(acc[p][1], wd[p * 4 + k], vdb[k]);
            }
    }

    #pragma unroll
    for (int p = 0; p < 4; p++) {
        const int co0 = cg * 8 + 2 * p;
        float a0, a1, c0, c1;
        unpk(acc[p][0], a0, a1);
        unpk(acc[p][1], c0, c1);
        if (j1 >= S) {
            float v0 = (gt0 + j1 < 0) ? 0.f : fmaxf(a0, 0.f);
            float v1 = (gt0 + j1 < 0) ? 0.f : fmaxf(a1, 0.f);
            out[co0 * PITCH + j1]       = v0;
            out[(co0 + 1) * PITCH + j1] = v1;
        }
        {
            float v0 = (gt0 + j2 < 0) ? 0.f : fmaxf(c0, 0.f);
            float v1 = (gt0 + j2 < 0) ? 0.f : fmaxf(c1, 0.f);
            out[co0 * PITCH + j2]       = v0;
            out[(co0 + 1) * PITCH + j2] = v1;
        }
    }
}

__global__ void __launch_bounds__(NTHREADS, 2)
navar_main_kernel(const float* __restrict__ x,
                  const float* __restrict__ w_in, const float* __restrict__ b_in,
                  const float* __restrict__ w_h,  const float* __restrict__ b_h,
                  const float* __restrict__ w_out,const float* __restrict__ b_out,
                  float* __restrict__ out_contrib)
{
    __shared__ Smem s;
    float* bufA = s.bufs + GUARD;
    float* bufB = bufA + HID * PITCH;
    float* xs   = s.xsb + 4;

    const int tile = blockIdx.x;
    const int g    = blockIdx.y;
    const int b    = blockIdx.z;
    const int t0   = tile * TT;
    const int gt0  = t0 - HALO;
    const int tid  = threadIdx.x;
    const int lane = tid & 31;
    const int wid  = tid >> 5;

    // ---- stage x tile + small params ----
    const float* xg = x + ((size_t)b * GROUPS + g) * T;
    for (int j = tid; j < PITCH; j += NTHREADS) {
        int gt = gt0 + j;
        xs[j] = (gt >= 0 && gt < T) ? xg[gt] : 0.f;
    }
    if (tid < HID * KS) s.w_in[tid] = w_in[g * HID * KS + tid];
    if (tid < HID)      s.b_in[tid] = b_in[g * HID + tid];
    for (int i = tid; i < 3 * HID; i += NTHREADS) {
        int L = i >> 4, co = i & 15;
        s.b_h[i] = b_h[L * GROUPS * HID + g * HID + co];
    }
    // output conv weights packed as dst pairs
    for (int i = tid; i < HID * 6 * 2; i += NTHREADS) {
        int half = i & 1, dp = (i >> 1) % 6, ci = (i >> 1) / 6;
        ((float*)s.woutp)[i] = w_out[((size_t)g * NV + 2 * dp + half) * HID + ci];
    }
    if (tid < 12) {
        int half = tid & 1, dp = tid >> 1;
        ((float*)s.boutp)[tid] = b_out[g * NV + 2 * dp + half];
    }
    __syncthreads();

    // ---- input conv 1 -> HID (thread = timestep j) ----
    {
        const int j = tid;
        float xv0 = xs[j - 3], xv1 = xs[j - 2], xv2 = xs[j - 1], xv3 = xs[j];
        const bool neg = (gt0 + j) < 0;
        #pragma unroll
        for (int co = 0; co < HID; co++) {
            float4 w = *(const float4*)(s.w_in + co * 4);
            float a = s.b_in[co];
            a = fmaf(w.x, xv0, a); a = fmaf(w.y, xv1, a);
            a = fmaf(w.z, xv2, a); a = fmaf(w.w, xv3, a);
            bufA[co * PITCH + j] = neg ? 0.f : fmaxf(a, 0.f);
        }
    }

    // ---- 3 dilated hidden layers ----
    #pragma unroll 1
    for (int L = 0; L < 3; L++) {
        __syncthreads();   // prev layer's compute done; whp free to overwrite
        const float* wsrc = w_h + ((size_t)L * GROUPS * HID + (size_t)g * HID) * (HID * KS);
        float* wdst = (float*)s.whp;
        for (int i = tid; i < HID * HID * KS; i += NTHREADS) {
            int half = i & 1, k = (i >> 1) & 3, pg = (i >> 3) & 7, ci = i >> 6;
            int co = 2 * pg + half;
            wdst[i] = wsrc[(co * HID + ci) * KS + k];
        }
        __syncthreads();
        if      (L == 0) hidden2<1,  8>(bufA, bufB, s.whp, s.b_h,           gt0, lane, wid);
        else if (L == 1) hidden2<2, 16>(bufB, bufA, s.whp, s.b_h + HID,     gt0, lane, wid);
        else             hidden2<4, 28>(bufA, bufB, s.whp, s.b_h + 2 * HID, gt0, lane, wid);
    }
    __syncthreads();

    // ---- 1x1 output conv: thread = timestep, all 12 dst packed as 6 pairs ----
    {
        const int dd  = g / (NS * NV);
        const int rem = g % (NS * NV);
        const int ss  = rem / NV;
        const int src = rem % NV;
        const size_t cbase = ((size_t)((b * ND + dd) * NS + ss) * NV * NV + src) * T;

        const int trel = tid;
        const int gt   = t0 + trel;
        const bool act = (trel < TT) && (gt < T);
        const int jc   = act ? (HALO + trel) : HALO;   // clamp inactive lanes in-bounds

        u64 a6[6];
        #pragma unroll
        for (int dp = 0; dp < 6; dp++) a6[dp] = s.boutp[dp];

        #pragma unroll
        for (int ci = 0; ci < HID; ci++) {
            u64 hd = dup2f(bufB[ci * PITCH + jc]);
            const ulonglong2* w2 = (const ulonglong2*)(s.woutp + ci * 6);
            ulonglong2 wA = w2[0], wB = w2[1], wC = w2[2];
            fma2(a6[0], wA.x, hd); fma2(a6[1], wA.y, hd);
            fma2(a6[2], wB.x, hd); fma2(a6[3], wB.y, hd);
            fma2(a6[4], wC.x, hd); fma2(a6[5], wC.y, hd);
        }
        if (act) {
            #pragma unroll
            for (int dp = 0; dp < 6; dp++) {
                float lo, hi; unpk(a6[dp], lo, hi);
                out_contrib[cbase + (size_t)(2 * dp)     * NV * T + gt] = lo;
                out_contrib[cbase + (size_t)(2 * dp + 1) * NV * T + gt] = hi;
            }
        }
    }
}

// prediction[b,dd,ss,v,t] = sum_src contrib[b,dd,ss,v,src,t] + biases[dd,ss,v]
__global__ void __launch_bounds__(256)
navar_pred_kernel(const float4* __restrict__ contrib4,
                  const float* __restrict__ biases,
                  float4* __restrict__ pred4)
{
    int idx = blockIdx.x * blockDim.x + threadIdx.x;
    if (idx >= PRED_ELEMS / 4) return;
    int t4 = idx & (T / 4 - 1);
    int r  = idx >> 9;                 // T/4 = 512
    float bsc = biases[r % (ND * NS * NV)];
    const float4* cp = contrib4 + (size_t)r * NV * (T / 4) + t4;
    float4 acc = make_float4(bsc, bsc, bsc, bsc);
    #pragma unroll
    for (int sI = 0; sI < NV; sI++) {
        float4 v = cp[(size_t)sI * (T / 4)];
        acc.x += v.x; acc.y += v.y; acc.z += v.z; acc.w += v.w;
    }
    pred4[idx] = acc;
}

extern "C" void kernel_launch(void* const* d_in, const int* in_sizes, int n_in,
                              void* d_out, int out_size)
{
    const float* x      = (const float*)d_in[0];
    const float* w_in   = (const float*)d_in[1];
    const float* b_in   = (const float*)d_in[2];
    const float* w_h    = (const float*)d_in[3];
    const float* b_h    = (const float*)d_in[4];
    const float* w_out  = (const float*)d_in[5];
    const float* b_out  = (const float*)d_in[6];
    const float* biases = (const float*)d_in[7];

    float* out     = (float*)d_out;
    float* pred    = out;                     // (B,ND,NS,NV,T)
    float* contrib = out + PRED_ELEMS;        // (B,ND,NS,NV,NV,T)

    dim3 grid(NTILES, GROUPS, BATCH);
    navar_main_kernel<<<grid, NTHREADS>>>(x, w_in, b_in, w_h, b_h, w_out, b_out, contrib);
    navar_pred_kernel<<<(PRED_ELEMS / 4 + 255) / 256, 256>>>(
        (const float4*)contrib, biases, (float4*)pred);
}